// round 13
// baseline (speedup 1.0000x reference)
#include <cuda_runtime.h>
#include <math.h>

#define BATCH   8
#define NPTS    4096
#define NBINS   128
#define CAP     192
#define XMIN    (-4.25f)
#define BINW    (8.5f / NBINS)           // 0.06640625, exact in binary
#define BININV  (NBINS / 8.5f)
#define NARR    (2 * BATCH)
#define WBINS   8                        // window half-width in bins
#define NCHUNK  (NPTS / 256)             // 16 query chunks per (dir,batch)
#define GSCAN   (2 * BATCH * NCHUNK)     // 256 scan blocks
#define NQ      (2 * BATCH * NPTS)
#define RBLK    64
#define SMSCAN  ((NPTS / 2) * 32)        // 65536 B: candidate pair quads only

__device__ float4   g_bins[NARR * NBINS * CAP];   // (t2, -2x, -2y, -2z)
__device__ int      g_cnt [NARR * NBINS];         // zero-init; reset by reduce
__device__ float    g_res [NQ];                   // per-query min sq dist
__device__ float    g_bsum[RBLK];
__device__ unsigned g_tick;                       // zero-init; self-reset

// ---- f32x2 helpers -------------------------------------------------------
__device__ __forceinline__ unsigned long long pk(float lo, float hi) {
    unsigned long long r;
    asm("mov.b64 %0, {%1, %2};" : "=l"(r)
        : "r"(__float_as_uint(lo)), "r"(__float_as_uint(hi)));
    return r;
}
__device__ __forceinline__ unsigned long long fma2(
    unsigned long long a, unsigned long long b, unsigned long long c) {
    unsigned long long d;
    asm("fma.rn.f32x2 %0, %1, %2, %3;" : "=l"(d) : "l"(a), "l"(b), "l"(c));
    return d;
}
__device__ __forceinline__ void unpk(unsigned long long v, float& lo, float& hi) {
    unsigned a, b;
    asm("mov.b64 {%0, %1}, %2;" : "=r"(a), "=r"(b) : "l"(v));
    lo = __uint_as_float(a);
    hi = __uint_as_float(b);
}

// ---- K1: scatter into x-bins (transformed quads) -------------------------
__global__ __launch_bounds__(256)
void scatter_kernel(const float* __restrict__ pred,
                    const float* __restrict__ target)
{
    int idx = blockIdx.x * 256 + threadIdx.x;   // 0..32767, 2 points each
    int pt  = idx * 2;
    int i   = pt & (NPTS - 1);
    int b   = (pt >> 12) & 7;
    int s   = pt >> 15;
    int a   = s * BATCH + b;
    const float2* p = (const float2*)((s ? target : pred) + ((size_t)b * NPTS + i) * 3);
    float2 f0 = p[0], f1 = p[1], f2 = p[2];

    float x0 = f0.x, y0 = f0.y, z0 = f1.x;
    float x1 = f1.y, y1 = f2.x, z1 = f2.y;

    int bin0 = min(max((int)floorf((x0 - XMIN) * BININV), 0), NBINS - 1);
    int bin1 = min(max((int)floorf((x1 - XMIN) * BININV), 0), NBINS - 1);
    int s0 = atomicAdd(&g_cnt[a * NBINS + bin0], 1);
    if (s0 < CAP)
        g_bins[(a * NBINS + bin0) * CAP + s0] =
            make_float4(x0*x0 + y0*y0 + z0*z0, -2.f*x0, -2.f*y0, -2.f*z0);
    int s1 = atomicAdd(&g_cnt[a * NBINS + bin1], 1);
    if (s1 < CAP)
        g_bins[(a * NBINS + bin1) * CAP + s1] =
            make_float4(x1*x1 + y1*y1 + z1*z1, -2.f*x1, -2.f*y1, -2.f*z1);
}

// ---- K2: windowed exact NN scan (R5 inner body, verify + inline fallback)
__global__ __launch_bounds__(256)
void scan_kernel()
{
    extern __shared__ unsigned char sraw[];
    ulonglong2* smu = (ulonglong2*)sraw;             // 2048 pair-quads (64 KB)
    float*      smf = (float*)sraw;
    __shared__ int cinc[NBINS];                      // incl prefix, candidates
    __shared__ int qinc[NBINS];                      // incl prefix, queries

    int tid   = threadIdx.x;
    int bid   = blockIdx.x;
    int chunk = bid & (NCHUNK - 1);
    int b     = (bid >> 4) & 7;
    int dir   = bid >> 7;
    int qa = dir * BATCH + b;
    int ca = (1 - dir) * BATCH + b;

    if (tid < NBINS) {
        cinc[tid] = min(g_cnt[ca * NBINS + tid], CAP);
        qinc[tid] = min(g_cnt[qa * NBINS + tid], CAP);
    }
    __syncthreads();
    for (int off = 1; off < NBINS; off <<= 1) {       // Hillis-Steele inclusive
        int vc = 0, vq = 0;
        if (tid < NBINS && tid >= off) { vc = cinc[tid - off]; vq = qinc[tid - off]; }
        __syncthreads();
        if (tid < NBINS && tid >= off) { cinc[tid] += vc; qinc[tid] += vq; }
        __syncthreads();
    }

    // stage candidates compacted + pair-packed (R5 smem layout)
    for (int idx = tid; idx < NBINS * CAP; idx += 256) {
        int bin  = idx / CAP;
        int slot = idx - bin * CAP;
        int st   = bin ? cinc[bin - 1] : 0;
        if (slot < cinc[bin] - st) {
            float4 c = g_bins[ca * NBINS * CAP + idx];
            int j = st + slot, pp = j >> 1, h = j & 1;
            smf[8 * pp + 0 + h] = c.x;
            smf[8 * pp + 2 + h] = c.y;
            smf[8 * pp + 4 + h] = c.z;
            smf[8 * pp + 6 + h] = c.w;
        }
    }
    int Nc = cinc[NBINS - 1];
    if (tid == 0 && (Nc & 1)) {                       // pad odd count with +inf
        int pp = Nc >> 1;
        smf[8 * pp + 1] = 3.0e38f;
        smf[8 * pp + 3] = 0.f; smf[8 * pp + 5] = 0.f; smf[8 * pp + 7] = 0.f;
    }
    __syncthreads();

    // this thread's query (bucket order)
    int gq = chunk * 256 + tid;
    int qb = 0;
    #pragma unroll
    for (int stp = 64; stp; stp >>= 1) {
        int nb = qb + stp;
        if (nb <= NBINS && qinc[nb - 1] <= gq) qb = nb;
    }
    if (qb >= NBINS) qb = NBINS - 1;                  // capped-count safety
    int qslot = gq - (qb ? qinc[qb - 1] : 0);
    qslot = min(max(qslot, 0), CAP - 1);              // capped-count safety
    float4 qp = g_bins[(qa * NBINS + qb) * CAP + qslot];
    float p2v = qp.x;
    float qx = -0.5f * qp.y, qy = -0.5f * qp.z, qz = -0.5f * qp.w;
    unsigned long long pxp = pk(qx, qx), pyp = pk(qy, qy), pzp = pk(qz, qz);

    // window in bins -> pair range; warp-uniform bounds (broadcast LDS)
    int lo = max(qb - WBINS, 0), hi = min(qb + WBINS, NBINS - 1);
    int cstart = lo ? cinc[lo - 1] : 0;
    int cend   = cinc[hi];
    int ps = (int)__reduce_min_sync(0xffffffffu, (unsigned)(cstart >> 1));
    int pe = (int)__reduce_max_sync(0xffffffffu, (unsigned)((cend + 1) >> 1));

    auto scanrange = [&](int a0i, int b0i) -> float {
        float m0 = 3.0e38f, m1 = 3.0e38f, m2 = 3.0e38f, m3 = 3.0e38f;
        int p = a0i;
        for (; p + 1 < b0i; p += 2) {
            ulonglong2 A0 = smu[2 * p + 0], B0 = smu[2 * p + 1];
            ulonglong2 A1 = smu[2 * p + 2], B1 = smu[2 * p + 3];
            unsigned long long v0 =
                fma2(B0.y, pzp, fma2(B0.x, pyp, fma2(A0.y, pxp, A0.x)));
            unsigned long long v1 =
                fma2(B1.y, pzp, fma2(B1.x, pyp, fma2(A1.y, pxp, A1.x)));
            float l0, h0, l1, h1;
            unpk(v0, l0, h0); unpk(v1, l1, h1);
            m0 = fminf(m0, l0); m1 = fminf(m1, h0);
            m2 = fminf(m2, l1); m3 = fminf(m3, h1);
        }
        if (p < b0i) {
            ulonglong2 A0 = smu[2 * p + 0], B0 = smu[2 * p + 1];
            unsigned long long v0 =
                fma2(B0.y, pzp, fma2(B0.x, pyp, fma2(A0.y, pxp, A0.x)));
            float l0, h0; unpk(v0, l0, h0);
            m0 = fminf(m0, l0); m1 = fminf(m1, h0);
        }
        return fminf(fminf(m0, m1), fminf(m2, m3));
    };

    float dall = scanrange(ps, pe) + p2v;             // squared dist (>= 0)

    // exact verification; inline full-smem fallback for rare tail queries
    float gL = qx - (XMIN + (float)lo * BINW);
    float gR = (XMIN + (float)(hi + 1) * BINW) - qx;
    bool ok = (lo == 0 || gL * gL >= dall) && (hi == NBINS - 1 || gR * gR >= dall);
    if (!ok)
        dall = fminf(dall, scanrange(0, (Nc + 1) >> 1) + p2v);

    g_res[(dir * BATCH + b) * NPTS + gq] = dall;      // exclusive writer
}

// ---- K3: sum + reset g_cnt + ticket finish -------------------------------
__global__ __launch_bounds__(256)
void reduce_kernel(float* __restrict__ out)
{
    __shared__ float wsum[8];
    __shared__ int   is_last;
    int tid = threadIdx.x;
    int i4  = (blockIdx.x * 256 + tid) * 4;

    float4 v = *(const float4*)&g_res[i4];
    float sum = (v.x + v.y) + (v.z + v.w);

    if (blockIdx.x == 0)                              // reset bin cursors
        for (int k = tid; k < NARR * NBINS; k += 256) g_cnt[k] = 0;

    #pragma unroll
    for (int off = 16; off > 0; off >>= 1)
        sum += __shfl_down_sync(0xffffffffu, sum, off);
    if ((tid & 31) == 0) wsum[tid >> 5] = sum;
    __syncthreads();

    if (tid == 0) {
        float s = 0.0f;
        #pragma unroll
        for (int w = 0; w < 8; w++) s += wsum[w];
        g_bsum[blockIdx.x] = s;
        __threadfence();
        is_last = (atomicAdd(&g_tick, 1u) == RBLK - 1);
    }
    __syncthreads();

    if (is_last && tid < 32) {
        __threadfence();
        float s = 0.0f;
        #pragma unroll
        for (int r = 0; r < RBLK / 32; r++)
            s += *((volatile float*)&g_bsum[r * 32 + tid]);
        #pragma unroll
        for (int off = 16; off > 0; off >>= 1)
            s += __shfl_down_sync(0xffffffffu, s, off);
        if (tid == 0) {
            out[0] = s * (1.0f / (float)(BATCH * NPTS));
            g_tick = 0;
        }
    }
}

extern "C" void kernel_launch(void* const* d_in, const int* in_sizes, int n_in,
                              void* d_out, int out_size)
{
    const float* pred   = (const float*)d_in[0];
    const float* target = (const float*)d_in[1];
    float* out = (float*)d_out;

    cudaFuncSetAttribute(scan_kernel,
                         cudaFuncAttributeMaxDynamicSharedMemorySize, SMSCAN);

    scatter_kernel<<<(2 * BATCH * NPTS / 2) / 256, 256>>>(pred, target);
    scan_kernel<<<GSCAN, 256, SMSCAN>>>();
    reduce_kernel<<<RBLK, 256>>>(out);
}

// round 14
// speedup vs baseline: 1.9904x; 1.9904x over previous
#include <cuda_runtime.h>

#define BATCH   8
#define NPTS    4096
#define THREADS 128
#define QBLK    4                        // queries per thread (regs ~72)
#define QCH     (QBLK * THREADS)         // 512 queries per block
#define QCHUNKS (NPTS / QCH)             // 8 query chunks per (dir,batch)
#define SPLIT   8                        // candidate splits
#define CTILE   (NPTS / SPLIT)           // 512 candidates per block
#define CPAIRS  (CTILE / 2)              // 256 packed candidate pairs
#define NQ      (2 * BATCH * NPTS)       // 65536 query slots (both dirs)
#define NBLK    (2 * BATCH * QCHUNKS * SPLIT)  // 1024 blocks

__device__ unsigned g_max[NQ];   // reversed order keys; 0 == +inf identity
__device__ unsigned g_tick;      // zero-init; self-reset each replay

// ---- f32x2 helpers -------------------------------------------------------
__device__ __forceinline__ unsigned long long pk(float lo, float hi) {
    unsigned long long r;
    asm("mov.b64 %0, {%1, %2};" : "=l"(r)
        : "r"(__float_as_uint(lo)), "r"(__float_as_uint(hi)));
    return r;
}
__device__ __forceinline__ unsigned long long fma2(
    unsigned long long a, unsigned long long b, unsigned long long c) {
    unsigned long long d;
    asm("fma.rn.f32x2 %0, %1, %2, %3;" : "=l"(d) : "l"(a), "l"(b), "l"(c));
    return d;
}
__device__ __forceinline__ void unpk(unsigned long long v, float& lo, float& hi) {
    unsigned a, b;
    asm("mov.b64 {%0, %1}, %2;" : "=r"(a), "=r"(b) : "l"(v));
    lo = __uint_as_float(a);
    hi = __uint_as_float(b);
}

// order-preserving float->uint key, REVERSED (smaller float -> larger key)
// so zero-initialized g_max is the identity for atomicMax
__device__ __forceinline__ unsigned rkey(float f) {
    unsigned u = __float_as_uint(f);
    unsigned k = (u >> 31) ? ~u : (u | 0x80000000u);
    return ~k;
}
__device__ __forceinline__ float rdecode(unsigned r) {
    unsigned k = ~r;
    unsigned u = (k >> 31) ? (k & 0x7FFFFFFFu) : ~k;
    return __uint_as_float(u);
}

// ---- single kernel: partial mins + lean ticket-counter final reduce ------
__global__ __launch_bounds__(THREADS, 5)
void chamfer_kernel(const float* __restrict__ pred,
                    const float* __restrict__ target,
                    float* __restrict__ out)
{
    // packed candidate pairs: sm[2k]=(t2 pair, -2x pair), sm[2k+1]=(-2y, -2z)
    __shared__ ulonglong2 sm[2 * CPAIRS];   // 8 KB
    __shared__ float      wsum[THREADS / 32];
    __shared__ int        is_last;

    int bid   = blockIdx.x;
    int s     = bid & (SPLIT - 1);
    int chunk = (bid >> 3) & (QCHUNKS - 1);
    int b     = (bid >> 6) & (BATCH - 1);
    int dir   = bid >> 9;

    const float* Q = dir ? target : pred;
    const float* C = dir ? pred   : target;

    int tid = threadIdx.x;

    // 4 query points per thread, stride-THREADS for coalescing
    int qbase = chunk * QCH + tid;
    unsigned long long pxp[QBLK], pyp[QBLK], pzp[QBLK];
    float p2[QBLK];
    #pragma unroll
    for (int q = 0; q < QBLK; q++) {
        const float* qp = Q + ((size_t)b * NPTS + qbase + q * THREADS) * 3;
        float px = qp[0], py = qp[1], pz = qp[2];
        p2[q]  = px * px + py * py + pz * pz;
        pxp[q] = pk(px, px);
        pyp[q] = pk(py, py);
        pzp[q] = pk(pz, pz);
    }

    // cooperative load + pack of this block's candidate tile (512 points)
    const float2* cb2 = (const float2*)(C + ((size_t)b * NPTS + s * CTILE) * 3);
    for (int k = tid; k < CPAIRS; k += THREADS) {
        float2 f0 = cb2[3 * k + 0];   // x0 y0
        float2 f1 = cb2[3 * k + 1];   // z0 x1
        float2 f2 = cb2[3 * k + 2];   // y1 z1
        float x0 = f0.x, y0 = f0.y, z0 = f1.x;
        float x1 = f1.y, y1 = f2.x, z1 = f2.y;
        float t20 = x0 * x0 + y0 * y0 + z0 * z0;
        float t21 = x1 * x1 + y1 * y1 + z1 * z1;
        sm[2 * k]     = make_ulonglong2(pk(t20, t21), pk(-2.f * x0, -2.f * x1));
        sm[2 * k + 1] = make_ulonglong2(pk(-2.f * y0, -2.f * y1), pk(-2.f * z0, -2.f * z1));
    }
    __syncthreads();

    float mlo[QBLK], mhi[QBLK];
    #pragma unroll
    for (int q = 0; q < QBLK; q++) { mlo[q] = 3.0e38f; mhi[q] = 3.0e38f; }

    #pragma unroll 2
    for (int k = 0; k < CPAIRS; k += 2) {
        ulonglong2 a0 = sm[2 * k + 0];
        ulonglong2 b0 = sm[2 * k + 1];
        ulonglong2 a1 = sm[2 * k + 2];
        ulonglong2 b1 = sm[2 * k + 3];
        #pragma unroll
        for (int q = 0; q < QBLK; q++) {
            unsigned long long v0 =
                fma2(b0.y, pzp[q], fma2(b0.x, pyp[q], fma2(a0.y, pxp[q], a0.x)));
            unsigned long long v1 =
                fma2(b1.y, pzp[q], fma2(b1.x, pyp[q], fma2(a1.y, pxp[q], a1.x)));
            float lo0, hi0, lo1, hi1;
            unpk(v0, lo0, hi0);
            unpk(v1, lo1, hi1);
            // tournament: halves the loop-carried FMNMX chain
            mlo[q] = fminf(mlo[q], fminf(lo0, lo1));
            mhi[q] = fminf(mhi[q], fminf(hi0, hi1));
        }
    }

    // fold into per-query global min (0 is the atomicMax identity -> no init)
    int qidx = (dir * BATCH + b) * NPTS + qbase;
    #pragma unroll
    for (int q = 0; q < QBLK; q++) {
        float m = fminf(mlo[q], mhi[q]) + p2[q];
        atomicMax(&g_max[qidx + q * THREADS], rkey(m));
    }

    // ---- ticket: last block performs the final reduction (lean regs) -----
    __threadfence();
    if (tid == 0)
        is_last = (atomicAdd(&g_tick, 1u) == NBLK - 1);
    __syncthreads();
    if (!is_last) return;

    __threadfence();
    float sum = 0.0f;
    uint4* g4 = (uint4*)g_max;
    for (int i = tid; i < NQ / 4; i += THREADS) {   // no unroll: keep regs low
        uint4 v = __ldcg(&g4[i]);
        __stcg(&g4[i], make_uint4(0u, 0u, 0u, 0u)); // reset for graph replay
        sum += (rdecode(v.x) + rdecode(v.y)) + (rdecode(v.z) + rdecode(v.w));
    }

    #pragma unroll
    for (int off = 16; off > 0; off >>= 1)
        sum += __shfl_down_sync(0xffffffffu, sum, off);
    if ((tid & 31) == 0) wsum[tid >> 5] = sum;
    __syncthreads();

    if (tid == 0) {
        float t = (wsum[0] + wsum[1]) + (wsum[2] + wsum[3]);
        out[0] = t * (1.0f / (float)(BATCH * NPTS));
        g_tick = 0;   // self-reset for next graph replay
    }
}

extern "C" void kernel_launch(void* const* d_in, const int* in_sizes, int n_in,
                              void* d_out, int out_size)
{
    const float* pred   = (const float*)d_in[0];
    const float* target = (const float*)d_in[1];
    float* out = (float*)d_out;

    chamfer_kernel<<<NBLK, THREADS>>>(pred, target, out);
}

// round 15
// speedup vs baseline: 2.1684x; 1.0895x over previous
#include <cuda_runtime.h>

#define BATCH   8
#define NPTS    4096
#define THREADS 128
#define QBLK    4                        // queries per thread (regs ~72)
#define QCH     (QBLK * THREADS)         // 512 queries per block
#define QCHUNKS (NPTS / QCH)             // 8 query chunks per (dir,batch)
#define SPLIT   8                        // candidate splits
#define CTILE   (NPTS / SPLIT)           // 512 candidates per block
#define CPAIRS  (CTILE / 2)              // 256 packed candidate pairs
#define NQ      (2 * BATCH * NPTS)       // 65536 query slots (both dirs)
#define NBLK    (2 * BATCH * QCHUNKS * SPLIT)  // 1024 blocks

__device__ unsigned g_max[NQ];   // reversed order keys; 0 == +inf identity
__device__ unsigned g_tick;      // zero-init; self-reset each replay

// ---- f32x2 helpers -------------------------------------------------------
__device__ __forceinline__ unsigned long long pk(float lo, float hi) {
    unsigned long long r;
    asm("mov.b64 %0, {%1, %2};" : "=l"(r)
        : "r"(__float_as_uint(lo)), "r"(__float_as_uint(hi)));
    return r;
}
__device__ __forceinline__ unsigned long long fma2(
    unsigned long long a, unsigned long long b, unsigned long long c) {
    unsigned long long d;
    asm("fma.rn.f32x2 %0, %1, %2, %3;" : "=l"(d) : "l"(a), "l"(b), "l"(c));
    return d;
}
__device__ __forceinline__ void unpk(unsigned long long v, float& lo, float& hi) {
    unsigned a, b;
    asm("mov.b64 {%0, %1}, %2;" : "=r"(a), "=r"(b) : "l"(v));
    lo = __uint_as_float(a);
    hi = __uint_as_float(b);
}

// order-preserving float->uint key, REVERSED (smaller float -> larger key)
// so zero-initialized g_max is the identity for atomicMax
__device__ __forceinline__ unsigned rkey(float f) {
    unsigned u = __float_as_uint(f);
    unsigned k = (u >> 31) ? ~u : (u | 0x80000000u);
    return ~k;
}
__device__ __forceinline__ float rdecode(unsigned r) {
    unsigned k = ~r;
    unsigned u = (k >> 31) ? (k & 0x7FFFFFFFu) : ~k;
    return __uint_as_float(u);
}

// ---- single kernel: partial mins + MLP-8 ticket-counter final reduce -----
__global__ __launch_bounds__(THREADS, 7)
void chamfer_kernel(const float* __restrict__ pred,
                    const float* __restrict__ target,
                    float* __restrict__ out)
{
    // packed candidate pairs: sm[2k]=(t2 pair, -2x pair), sm[2k+1]=(-2y, -2z)
    __shared__ ulonglong2 sm[2 * CPAIRS];   // 8 KB
    __shared__ float      wsum[THREADS / 32];
    __shared__ int        is_last;

    int bid   = blockIdx.x;
    int s     = bid & (SPLIT - 1);
    int chunk = (bid >> 3) & (QCHUNKS - 1);
    int b     = (bid >> 6) & (BATCH - 1);
    int dir   = bid >> 9;

    const float* Q = dir ? target : pred;
    const float* C = dir ? pred   : target;

    int tid = threadIdx.x;

    // 4 query points per thread, stride-THREADS for coalescing
    int qbase = chunk * QCH + tid;
    unsigned long long pxp[QBLK], pyp[QBLK], pzp[QBLK];
    float p2[QBLK];
    #pragma unroll
    for (int q = 0; q < QBLK; q++) {
        const float* qp = Q + ((size_t)b * NPTS + qbase + q * THREADS) * 3;
        float px = qp[0], py = qp[1], pz = qp[2];
        p2[q]  = px * px + py * py + pz * pz;
        pxp[q] = pk(px, px);
        pyp[q] = pk(py, py);
        pzp[q] = pk(pz, pz);
    }

    // cooperative load + pack of this block's candidate tile (512 points)
    const float2* cb2 = (const float2*)(C + ((size_t)b * NPTS + s * CTILE) * 3);
    for (int k = tid; k < CPAIRS; k += THREADS) {
        float2 f0 = cb2[3 * k + 0];   // x0 y0
        float2 f1 = cb2[3 * k + 1];   // z0 x1
        float2 f2 = cb2[3 * k + 2];   // y1 z1
        float x0 = f0.x, y0 = f0.y, z0 = f1.x;
        float x1 = f1.y, y1 = f2.x, z1 = f2.y;
        float t20 = x0 * x0 + y0 * y0 + z0 * z0;
        float t21 = x1 * x1 + y1 * y1 + z1 * z1;
        sm[2 * k]     = make_ulonglong2(pk(t20, t21), pk(-2.f * x0, -2.f * x1));
        sm[2 * k + 1] = make_ulonglong2(pk(-2.f * y0, -2.f * y1), pk(-2.f * z0, -2.f * z1));
    }
    __syncthreads();

    float mlo[QBLK], mhi[QBLK];
    #pragma unroll
    for (int q = 0; q < QBLK; q++) { mlo[q] = 3.0e38f; mhi[q] = 3.0e38f; }

    #pragma unroll 2
    for (int k = 0; k < CPAIRS; k += 2) {
        ulonglong2 a0 = sm[2 * k + 0];
        ulonglong2 b0 = sm[2 * k + 1];
        ulonglong2 a1 = sm[2 * k + 2];
        ulonglong2 b1 = sm[2 * k + 3];
        #pragma unroll
        for (int q = 0; q < QBLK; q++) {
            unsigned long long v0 =
                fma2(b0.y, pzp[q], fma2(b0.x, pyp[q], fma2(a0.y, pxp[q], a0.x)));
            unsigned long long v1 =
                fma2(b1.y, pzp[q], fma2(b1.x, pyp[q], fma2(a1.y, pxp[q], a1.x)));
            float lo0, hi0, lo1, hi1;
            unpk(v0, lo0, hi0);
            unpk(v1, lo1, hi1);
            // tournament: halves the loop-carried FMNMX chain
            mlo[q] = fminf(mlo[q], fminf(lo0, lo1));
            mhi[q] = fminf(mhi[q], fminf(hi0, hi1));
        }
    }

    // fold into per-query global min (0 is the atomicMax identity -> no init)
    int qidx = (dir * BATCH + b) * NPTS + qbase;
    #pragma unroll
    for (int q = 0; q < QBLK; q++) {
        float m = fminf(mlo[q], mhi[q]) + p2[q];
        atomicMax(&g_max[qidx + q * THREADS], rkey(m));
    }

    // ---- ticket: last block performs the final reduction -----------------
    __threadfence();
    if (tid == 0)
        is_last = (atomicAdd(&g_tick, 1u) == NBLK - 1);
    __syncthreads();
    if (!is_last) return;

    __threadfence();
    // 16384 uint4, 128 threads, batches of 8 outstanding LDG.128 per thread
    float s0 = 0.f, s1 = 0.f, s2 = 0.f, s3 = 0.f;
    uint4* g4 = (uint4*)g_max;
    for (int base = tid; base < NQ / 4; base += THREADS * 8) {
        uint4 v[8];
        #pragma unroll
        for (int u = 0; u < 8; u++)
            v[u] = __ldcg(&g4[base + u * THREADS]);
        #pragma unroll
        for (int u = 0; u < 8; u++)
            __stcg(&g4[base + u * THREADS], make_uint4(0u, 0u, 0u, 0u));
        #pragma unroll
        for (int u = 0; u < 8; u++) {
            s0 += rdecode(v[u].x);
            s1 += rdecode(v[u].y);
            s2 += rdecode(v[u].z);
            s3 += rdecode(v[u].w);
        }
    }
    float sum = (s0 + s1) + (s2 + s3);

    #pragma unroll
    for (int off = 16; off > 0; off >>= 1)
        sum += __shfl_down_sync(0xffffffffu, sum, off);
    if ((tid & 31) == 0) wsum[tid >> 5] = sum;
    __syncthreads();

    if (tid == 0) {
        float t = (wsum[0] + wsum[1]) + (wsum[2] + wsum[3]);
        out[0] = t * (1.0f / (float)(BATCH * NPTS));
        g_tick = 0;   // self-reset for next graph replay
    }
}

extern "C" void kernel_launch(void* const* d_in, const int* in_sizes, int n_in,
                              void* d_out, int out_size)
{
    const float* pred   = (const float*)d_in[0];
    const float* target = (const float*)d_in[1];
    float* out = (float*)d_out;

    chamfer_kernel<<<NBLK, THREADS>>>(pred, target, out);
}

// round 16
// speedup vs baseline: 2.5941x; 1.1963x over previous
#include <cuda_runtime.h>

#define BATCH   8
#define NPTS    4096
#define THREADS 128
#define QBLK    8                        // queries per thread
#define QCH     (QBLK * THREADS)         // 1024 queries per block/group
#define QCHUNKS (NPTS / QCH)             // 4 query chunks per (dir,batch)
#define SPLIT   16                       // candidate splits (blocks per group)
#define CTILE   (NPTS / SPLIT)           // 256 candidates per block
#define CPAIRS  (CTILE / 2)              // 128 packed candidate pairs
#define NQ      (2 * BATCH * NPTS)       // 65536 query slots (both dirs)
#define NGRP    (2 * BATCH * QCHUNKS)    // 64 groups
#define NBLK    (NGRP * SPLIT)           // 1024 blocks

__device__ unsigned g_max[NQ];      // reversed order keys; 0 == +inf identity
__device__ unsigned g_gtick[NGRP];  // per-group tickets; self-reset
__device__ float    g_bsum[NGRP];   // per-group sums
__device__ unsigned g_tick;         // global ticket; self-reset

// ---- f32x2 helpers -------------------------------------------------------
__device__ __forceinline__ unsigned long long pk(float lo, float hi) {
    unsigned long long r;
    asm("mov.b64 %0, {%1, %2};" : "=l"(r)
        : "r"(__float_as_uint(lo)), "r"(__float_as_uint(hi)));
    return r;
}
__device__ __forceinline__ unsigned long long fma2(
    unsigned long long a, unsigned long long b, unsigned long long c) {
    unsigned long long d;
    asm("fma.rn.f32x2 %0, %1, %2, %3;" : "=l"(d) : "l"(a), "l"(b), "l"(c));
    return d;
}
__device__ __forceinline__ void unpk(unsigned long long v, float& lo, float& hi) {
    unsigned a, b;
    asm("mov.b64 {%0, %1}, %2;" : "=r"(a), "=r"(b) : "l"(v));
    lo = __uint_as_float(a);
    hi = __uint_as_float(b);
}

// order-preserving float->uint key, REVERSED (smaller float -> larger key)
// so zero-initialized g_max is the identity for atomicMax
__device__ __forceinline__ unsigned rkey(float f) {
    unsigned u = __float_as_uint(f);
    unsigned k = (u >> 31) ? ~u : (u | 0x80000000u);
    return ~k;
}
__device__ __forceinline__ float rdecode(unsigned r) {
    unsigned k = ~r;
    unsigned u = (k >> 31) ? (k & 0x7FFFFFFFu) : ~k;
    return __uint_as_float(u);
}

// ---- single kernel: R5 main loop + hierarchical ticket reduction ---------
__global__ __launch_bounds__(THREADS, 4)
void chamfer_kernel(const float* __restrict__ pred,
                    const float* __restrict__ target,
                    float* __restrict__ out)
{
    // packed candidate pairs: sm[2k]=(t2 pair, -2x pair), sm[2k+1]=(-2y, -2z)
    __shared__ ulonglong2 sm[2 * CPAIRS];   // 4 KB
    __shared__ float      wsum[THREADS / 32];
    __shared__ int        is_glast, is_final;

    int bid   = blockIdx.x;
    int s     = bid & (SPLIT - 1);
    int grp   = bid >> 4;                 // 0..63
    int chunk = grp & (QCHUNKS - 1);
    int b     = (grp >> 2) & (BATCH - 1);
    int dir   = grp >> 5;

    const float* Q = dir ? target : pred;
    const float* C = dir ? pred   : target;

    int tid = threadIdx.x;

    // 8 query points per thread, stride-THREADS for coalescing
    int qbase = chunk * QCH + tid;
    unsigned long long pxp[QBLK], pyp[QBLK], pzp[QBLK];
    float p2[QBLK];
    #pragma unroll
    for (int q = 0; q < QBLK; q++) {
        const float* qp = Q + ((size_t)b * NPTS + qbase + q * THREADS) * 3;
        float px = qp[0], py = qp[1], pz = qp[2];
        p2[q]  = px * px + py * py + pz * pz;
        pxp[q] = pk(px, px);
        pyp[q] = pk(py, py);
        pzp[q] = pk(pz, pz);
    }

    // cooperative load + pack of this block's candidate tile (256 points)
    const float2* cb2 = (const float2*)(C + ((size_t)b * NPTS + s * CTILE) * 3);
    for (int k = tid; k < CPAIRS; k += THREADS) {
        float2 f0 = cb2[3 * k + 0];   // x0 y0
        float2 f1 = cb2[3 * k + 1];   // z0 x1
        float2 f2 = cb2[3 * k + 2];   // y1 z1
        float x0 = f0.x, y0 = f0.y, z0 = f1.x;
        float x1 = f1.y, y1 = f2.x, z1 = f2.y;
        float t20 = x0 * x0 + y0 * y0 + z0 * z0;
        float t21 = x1 * x1 + y1 * y1 + z1 * z1;
        sm[2 * k]     = make_ulonglong2(pk(t20, t21), pk(-2.f * x0, -2.f * x1));
        sm[2 * k + 1] = make_ulonglong2(pk(-2.f * y0, -2.f * y1), pk(-2.f * z0, -2.f * z1));
    }
    __syncthreads();

    float mlo[QBLK], mhi[QBLK];
    #pragma unroll
    for (int q = 0; q < QBLK; q++) { mlo[q] = 3.0e38f; mhi[q] = 3.0e38f; }

    #pragma unroll 2
    for (int k = 0; k < CPAIRS; k += 2) {
        ulonglong2 a0 = sm[2 * k + 0];
        ulonglong2 b0 = sm[2 * k + 1];
        ulonglong2 a1 = sm[2 * k + 2];
        ulonglong2 b1 = sm[2 * k + 3];
        #pragma unroll
        for (int q = 0; q < QBLK; q++) {
            unsigned long long v0 =
                fma2(b0.y, pzp[q], fma2(b0.x, pyp[q], fma2(a0.y, pxp[q], a0.x)));
            unsigned long long v1 =
                fma2(b1.y, pzp[q], fma2(b1.x, pyp[q], fma2(a1.y, pxp[q], a1.x)));
            float lo0, hi0, lo1, hi1;
            unpk(v0, lo0, hi0);
            unpk(v1, lo1, hi1);
            mlo[q] = fminf(mlo[q], fminf(lo0, lo1));
            mhi[q] = fminf(mhi[q], fminf(hi0, hi1));
        }
    }

    // fold into per-query global min (0 is the atomicMax identity -> no init)
    int qstart = (dir * BATCH + b) * NPTS + chunk * QCH;   // group's 1024 slots
    #pragma unroll
    for (int q = 0; q < QBLK; q++) {
        float m = fminf(mlo[q], mhi[q]) + p2[q];
        atomicMax(&g_max[qstart + tid + q * THREADS], rkey(m));
    }

    // ---- group ticket: last-of-16 block reduces its 1024 slots -----------
    __threadfence();
    if (tid == 0)
        is_glast = (atomicAdd(&g_gtick[grp], 1u) == SPLIT - 1);
    __syncthreads();
    if (!is_glast) return;

    __threadfence();
    uint4* g4 = (uint4*)&g_max[qstart];   // 256 uint4, 2 per thread
    uint4 v0 = __ldcg(&g4[tid]);
    uint4 v1 = __ldcg(&g4[tid + THREADS]);
    __stcg(&g4[tid],           make_uint4(0u, 0u, 0u, 0u));  // reset for replay
    __stcg(&g4[tid + THREADS], make_uint4(0u, 0u, 0u, 0u));
    float sum = ((rdecode(v0.x) + rdecode(v0.y)) + (rdecode(v0.z) + rdecode(v0.w)))
              + ((rdecode(v1.x) + rdecode(v1.y)) + (rdecode(v1.z) + rdecode(v1.w)));

    #pragma unroll
    for (int off = 16; off > 0; off >>= 1)
        sum += __shfl_down_sync(0xffffffffu, sum, off);
    if ((tid & 31) == 0) wsum[tid >> 5] = sum;
    __syncthreads();

    if (tid == 0) {
        g_bsum[grp]  = (wsum[0] + wsum[1]) + (wsum[2] + wsum[3]);
        g_gtick[grp] = 0;                 // reset group ticket for replay
        __threadfence();
        is_final = (atomicAdd(&g_tick, 1u) == NGRP - 1);
    }
    __syncthreads();
    if (!is_final) return;

    // ---- final: sum 64 group sums ----------------------------------------
    if (tid < 32) {
        __threadfence();
        float t = *((volatile float*)&g_bsum[tid])
                + *((volatile float*)&g_bsum[tid + 32]);
        #pragma unroll
        for (int off = 16; off > 0; off >>= 1)
            t += __shfl_down_sync(0xffffffffu, t, off);
        if (tid == 0) {
            out[0] = t * (1.0f / (float)(BATCH * NPTS));
            g_tick = 0;                   // reset global ticket for replay
        }
    }
}

extern "C" void kernel_launch(void* const* d_in, const int* in_sizes, int n_in,
                              void* d_out, int out_size)
{
    const float* pred   = (const float*)d_in[0];
    const float* target = (const float*)d_in[1];
    float* out = (float*)d_out;

    chamfer_kernel<<<NBLK, THREADS>>>(pred, target, out);
}

// round 17
// speedup vs baseline: 2.6134x; 1.0074x over previous
#include <cuda_runtime.h>

#define BATCH   8
#define NPTS    4096
#define THREADS 128
#define QBLK    8                        // queries per thread
#define QCH     (QBLK * THREADS)         // 1024 queries per block/group
#define QCHUNKS (NPTS / QCH)             // 4 query chunks per (dir,batch)
#define SPLIT   16                       // candidate splits (blocks per group)
#define CTILE   (NPTS / SPLIT)           // 256 candidates per block
#define CPAIRS  (CTILE / 2)              // 128 packed candidate pairs
#define NQ      (2 * BATCH * NPTS)       // 65536 query slots (both dirs)
#define NGRP    (2 * BATCH * QCHUNKS)    // 64 groups
#define NBLK    (NGRP * SPLIT)           // 1024 blocks

__device__ unsigned g_max[NQ];      // reversed order keys; 0 == +inf identity
__device__ unsigned g_gtick[NGRP];  // per-group tickets; self-reset
__device__ float    g_bsum[NGRP];   // per-group sums
__device__ unsigned g_tick;         // global ticket; self-reset

// ---- f32x2 helpers -------------------------------------------------------
__device__ __forceinline__ unsigned long long pk(float lo, float hi) {
    unsigned long long r;
    asm("mov.b64 %0, {%1, %2};" : "=l"(r)
        : "r"(__float_as_uint(lo)), "r"(__float_as_uint(hi)));
    return r;
}
__device__ __forceinline__ unsigned long long fma2(
    unsigned long long a, unsigned long long b, unsigned long long c) {
    unsigned long long d;
    asm("fma.rn.f32x2 %0, %1, %2, %3;" : "=l"(d) : "l"(a), "l"(b), "l"(c));
    return d;
}
__device__ __forceinline__ void unpk(unsigned long long v, float& lo, float& hi) {
    unsigned a, b;
    asm("mov.b64 {%0, %1}, %2;" : "=r"(a), "=r"(b) : "l"(v));
    lo = __uint_as_float(a);
    hi = __uint_as_float(b);
}

// order-preserving float->uint key, REVERSED (smaller float -> larger key)
// so zero-initialized g_max is the identity for atomicMax
__device__ __forceinline__ unsigned rkey(float f) {
    unsigned u = __float_as_uint(f);
    unsigned k = (u >> 31) ? ~u : (u | 0x80000000u);
    return ~k;
}
__device__ __forceinline__ float rdecode(unsigned r) {
    unsigned k = ~r;
    unsigned u = (k >> 31) ? (k & 0x7FFFFFFFu) : ~k;
    return __uint_as_float(u);
}

// ---- tail: group-last reduction + final sum (isolated from main loop) ----
__device__ __noinline__ void group_tail(int tid, int grp, int qstart,
                                        float* __restrict__ out)
{
    __shared__ float wsum[THREADS / 32];
    __shared__ int   is_final;

    __threadfence();
    uint4* g4 = (uint4*)&g_max[qstart];   // 256 uint4, 2 per thread
    uint4 v0 = __ldcg(&g4[tid]);
    uint4 v1 = __ldcg(&g4[tid + THREADS]);
    __stcg(&g4[tid],           make_uint4(0u, 0u, 0u, 0u));  // reset for replay
    __stcg(&g4[tid + THREADS], make_uint4(0u, 0u, 0u, 0u));
    float sum = ((rdecode(v0.x) + rdecode(v0.y)) + (rdecode(v0.z) + rdecode(v0.w)))
              + ((rdecode(v1.x) + rdecode(v1.y)) + (rdecode(v1.z) + rdecode(v1.w)));

    #pragma unroll
    for (int off = 16; off > 0; off >>= 1)
        sum += __shfl_down_sync(0xffffffffu, sum, off);
    if ((tid & 31) == 0) wsum[tid >> 5] = sum;
    __syncthreads();

    if (tid == 0) {
        g_bsum[grp]  = (wsum[0] + wsum[1]) + (wsum[2] + wsum[3]);
        g_gtick[grp] = 0;                 // reset group ticket for replay
        __threadfence();
        is_final = (atomicAdd(&g_tick, 1u) == NGRP - 1);
    }
    __syncthreads();
    if (!is_final) return;

    // final: deterministic sum of 64 group sums
    if (tid < 32) {
        __threadfence();
        float t = *((volatile float*)&g_bsum[tid])
                + *((volatile float*)&g_bsum[tid + 32]);
        #pragma unroll
        for (int off = 16; off > 0; off >>= 1)
            t += __shfl_down_sync(0xffffffffu, t, off);
        if (tid == 0) {
            out[0] = t * (1.0f / (float)(BATCH * NPTS));
            g_tick = 0;                   // reset global ticket for replay
        }
    }
}

// ---- single kernel: R5 main loop + hierarchical ticket reduction ---------
__global__ __launch_bounds__(THREADS, 4)
void chamfer_kernel(const float* __restrict__ pred,
                    const float* __restrict__ target,
                    float* __restrict__ out)
{
    // packed candidate pairs: sm[2k]=(t2 pair, -2x pair), sm[2k+1]=(-2y, -2z)
    __shared__ ulonglong2 sm[2 * CPAIRS];   // 4 KB
    __shared__ int        is_glast;

    int bid   = blockIdx.x;
    int s     = bid & (SPLIT - 1);
    int grp   = bid >> 4;                 // 0..63
    int chunk = grp & (QCHUNKS - 1);
    int b     = (grp >> 2) & (BATCH - 1);
    int dir   = grp >> 5;

    const float* Q = dir ? target : pred;
    const float* C = dir ? pred   : target;

    int tid = threadIdx.x;

    // 8 query points per thread, stride-THREADS for coalescing
    int qbase = chunk * QCH + tid;
    unsigned long long pxp[QBLK], pyp[QBLK], pzp[QBLK];
    float p2[QBLK];
    #pragma unroll
    for (int q = 0; q < QBLK; q++) {
        const float* qp = Q + ((size_t)b * NPTS + qbase + q * THREADS) * 3;
        float px = qp[0], py = qp[1], pz = qp[2];
        p2[q]  = px * px + py * py + pz * pz;
        pxp[q] = pk(px, px);
        pyp[q] = pk(py, py);
        pzp[q] = pk(pz, pz);
    }

    // cooperative load + pack of this block's candidate tile (256 points)
    const float2* cb2 = (const float2*)(C + ((size_t)b * NPTS + s * CTILE) * 3);
    for (int k = tid; k < CPAIRS; k += THREADS) {
        float2 f0 = cb2[3 * k + 0];   // x0 y0
        float2 f1 = cb2[3 * k + 1];   // z0 x1
        float2 f2 = cb2[3 * k + 2];   // y1 z1
        float x0 = f0.x, y0 = f0.y, z0 = f1.x;
        float x1 = f1.y, y1 = f2.x, z1 = f2.y;
        float t20 = x0 * x0 + y0 * y0 + z0 * z0;
        float t21 = x1 * x1 + y1 * y1 + z1 * z1;
        sm[2 * k]     = make_ulonglong2(pk(t20, t21), pk(-2.f * x0, -2.f * x1));
        sm[2 * k + 1] = make_ulonglong2(pk(-2.f * y0, -2.f * y1), pk(-2.f * z0, -2.f * z1));
    }
    __syncthreads();

    float mlo[QBLK], mhi[QBLK];
    #pragma unroll
    for (int q = 0; q < QBLK; q++) { mlo[q] = 3.0e38f; mhi[q] = 3.0e38f; }

    #pragma unroll 2
    for (int k = 0; k < CPAIRS; k += 2) {
        ulonglong2 a0 = sm[2 * k + 0];
        ulonglong2 b0 = sm[2 * k + 1];
        ulonglong2 a1 = sm[2 * k + 2];
        ulonglong2 b1 = sm[2 * k + 3];
        #pragma unroll
        for (int q = 0; q < QBLK; q++) {
            unsigned long long v0 =
                fma2(b0.y, pzp[q], fma2(b0.x, pyp[q], fma2(a0.y, pxp[q], a0.x)));
            unsigned long long v1 =
                fma2(b1.y, pzp[q], fma2(b1.x, pyp[q], fma2(a1.y, pxp[q], a1.x)));
            float lo0, hi0, lo1, hi1;
            unpk(v0, lo0, hi0);
            unpk(v1, lo1, hi1);
            mlo[q] = fminf(mlo[q], fminf(lo0, lo1));
            mhi[q] = fminf(mhi[q], fminf(hi0, hi1));
        }
    }

    // fold into per-query global min (0 is the atomicMax identity -> no init)
    int qstart = (dir * BATCH + b) * NPTS + chunk * QCH;   // group's 1024 slots
    #pragma unroll
    for (int q = 0; q < QBLK; q++) {
        float m = fminf(mlo[q], mhi[q]) + p2[q];
        atomicMax(&g_max[qstart + tid + q * THREADS], rkey(m));
    }

    // ---- group ticket: last-of-16 block runs the isolated tail -----------
    __threadfence();
    if (tid == 0)
        is_glast = (atomicAdd(&g_gtick[grp], 1u) == SPLIT - 1);
    __syncthreads();
    if (!is_glast) return;

    group_tail(tid, grp, qstart, out);
}

extern "C" void kernel_launch(void* const* d_in, const int* in_sizes, int n_in,
                              void* d_out, int out_size)
{
    const float* pred   = (const float*)d_in[0];
    const float* target = (const float*)d_in[1];
    float* out = (float*)d_out;

    chamfer_kernel<<<NBLK, THREADS>>>(pred, target, out);
}